// round 10
// baseline (speedup 1.0000x reference)
#include <cuda_runtime.h>
#include <math.h>

#define LSEQ   4096
#define NPAIR  2048      // 16*256/2
#define TPB    512

static __device__ float2 g_Ksp[LSEQ];

// base-8, 4-digit reversal
__device__ __forceinline__ int digitrev84(int i) {
    return ((i & 7) << 9) | (((i >> 3) & 7) << 6) |
           (((i >> 6) & 7) << 3) | ((i >> 9) & 7);
}

// ---------------- fused K + Ksp kernel (all fp32) ----------------
// 16 lanes per k (4 states each); each group handles k and mirror L-k.
__global__ void compute_K_fused(const float* __restrict__ lre, const float* __restrict__ lim,
                                const float* __restrict__ pre, const float* __restrict__ pim,
                                const float* __restrict__ bre, const float* __restrict__ bim,
                                const float* __restrict__ cre, const float* __restrict__ cim)
{
    int gtid = blockIdx.x * blockDim.x + threadIdx.x;
    int k    = gtid >> 4;           // 0..2048
    int sub  = gtid & 15;
    if (k > LSEQ / 2) return;

    const float t = tanf((float)k * 7.6699039394282221e-4f);  // pi/4096
    const float G = 2000.0f * t;

    float a00r=0,a00i=0,a01r=0,a01i=0,a10r=0,a10i=0,a11r=0,a11i=0;
    float b00r=0,b00i=0,b01r=0,b01i=0,b10r=0,b10i=0,b11r=0,b11i=0;

    #pragma unroll
    for (int j = 0; j < 4; j++) {
        int n = sub * 4 + j;
        float lr = lre[n], li = lim[n];
        float pr = pre[n], pi_ = pim[n];
        float br = bre[n], bi = bim[n];
        float cr = cre[n], ci = cim[n];

        float nbr = fmaf(cr, br,  ci * bi),  nbi = fmaf(cr, bi, -ci * br);
        float npr = fmaf(cr, pr,  ci * pi_), npi = fmaf(cr, pi_, -ci * pr);
        float pbr = fmaf(pr, br,  pi_ * bi), pbi = fmaf(pr, bi, -pi_ * br);
        float pp  = fmaf(pr, pr,  pi_ * pi_);

        {
            float ex = -lr, ey = G - li;
            float r  = 1.0f / fmaf(ex, ex, ey * ey);
            float dr = ex * r, di = -ey * r;
            a00r = fmaf(dr, nbr, fmaf(-di, nbi, a00r));
            a00i = fmaf(dr, nbi, fmaf( di, nbr, a00i));
            a01r = fmaf(dr, npr, fmaf(-di, npi, a01r));
            a01i = fmaf(dr, npi, fmaf( di, npr, a01i));
            a10r = fmaf(dr, pbr, fmaf(-di, pbi, a10r));
            a10i = fmaf(dr, pbi, fmaf( di, pbr, a10i));
            a11r = fmaf(dr, pp, a11r);
            a11i = fmaf(di, pp, a11i);
        }
        {
            float ex = -lr, ey = -G - li;
            float r  = 1.0f / fmaf(ex, ex, ey * ey);
            float dr = ex * r, di = -ey * r;
            b00r = fmaf(dr, nbr, fmaf(-di, nbi, b00r));
            b00i = fmaf(dr, nbi, fmaf( di, nbr, b00i));
            b01r = fmaf(dr, npr, fmaf(-di, npi, b01r));
            b01i = fmaf(dr, npi, fmaf( di, npr, b01i));
            b10r = fmaf(dr, pbr, fmaf(-di, pbi, b10r));
            b10i = fmaf(dr, pbi, fmaf( di, pbr, b10i));
            b11r = fmaf(dr, pp, b11r);
            b11i = fmaf(di, pp, b11i);
        }
    }

    #pragma unroll
    for (int m = 1; m < 16; m <<= 1) {
        a00r += __shfl_xor_sync(0xffffffffu, a00r, m);
        a00i += __shfl_xor_sync(0xffffffffu, a00i, m);
        a01r += __shfl_xor_sync(0xffffffffu, a01r, m);
        a01i += __shfl_xor_sync(0xffffffffu, a01i, m);
        a10r += __shfl_xor_sync(0xffffffffu, a10r, m);
        a10i += __shfl_xor_sync(0xffffffffu, a10i, m);
        a11r += __shfl_xor_sync(0xffffffffu, a11r, m);
        a11i += __shfl_xor_sync(0xffffffffu, a11i, m);
        b00r += __shfl_xor_sync(0xffffffffu, b00r, m);
        b00i += __shfl_xor_sync(0xffffffffu, b00i, m);
        b01r += __shfl_xor_sync(0xffffffffu, b01r, m);
        b01i += __shfl_xor_sync(0xffffffffu, b01i, m);
        b10r += __shfl_xor_sync(0xffffffffu, b10r, m);
        b10i += __shfl_xor_sync(0xffffffffu, b10i, m);
        b11r += __shfl_xor_sync(0xffffffffu, b11r, m);
        b11i += __shfl_xor_sync(0xffffffffu, b11i, m);
    }

    if (sub == 0) {
        float Kk_r, Kk_i, Km_r, Km_i;
        {
            float numr = a01r * a10r - a01i * a10i;
            float numi = a01r * a10i + a01i * a10r;
            float der  = 1.0f + a11r, dei = a11i;
            float dd   = 1.0f / fmaf(der, der, dei * dei);
            float ar = a00r - (numr * der + numi * dei) * dd;
            float ai = a00i - (numi * der - numr * dei) * dd;
            Kk_r = fmaf(-t, ai, ar); Kk_i = fmaf(t, ar, ai);
        }
        {
            float numr = b01r * b10r - b01i * b10i;
            float numi = b01r * b10i + b01i * b10r;
            float der  = 1.0f + b11r, dei = b11i;
            float dd   = 1.0f / fmaf(der, der, dei * dei);
            float ar = b00r - (numr * der + numi * dei) * dd;
            float ai = b00i - (numi * der - numr * dei) * dd;
            Km_r = fmaf(t, ai, ar); Km_i = fmaf(-t, ar, ai);
        }
        const float sc = 0.5f / (float)LSEQ;
        float sr = (Kk_r + Km_r) * sc;
        float si = (Kk_i - Km_i) * sc;
        int mk = (LSEQ - k) & (LSEQ - 1);
        g_Ksp[digitrev84(k)]  = make_float2(sr,  si);
        g_Ksp[digitrev84(mk)] = make_float2(sr, -si);
    }
}

// ---------------- fp32 FFT machinery ----------------
// XOR swizzle: conflict-free for stride-512, stride-64 and stride-8 phases.
#define SWZ(i) ((i) ^ (((i) >> 3) & 0x38))

// Packed f32x2 complex add/sub (Blackwell FADD2/FFMA2).
__device__ __forceinline__ float2 f2add(float2 a, float2 b){
    float2 r;
    asm("{\n\t"
        ".reg .b64 ra, rb, rc;\n\t"
        "mov.b64 ra, {%2, %3};\n\t"
        "mov.b64 rb, {%4, %5};\n\t"
        "add.rn.f32x2 rc, ra, rb;\n\t"
        "mov.b64 {%0, %1}, rc;\n\t"
        "}"
        : "=f"(r.x), "=f"(r.y)
        : "f"(a.x), "f"(a.y), "f"(b.x), "f"(b.y));
    return r;
}
__device__ __forceinline__ float2 f2sub(float2 a, float2 b){
    float2 r;
    asm("{\n\t"
        ".reg .b64 ra, rb, rc, rn;\n\t"
        "mov.b64 rn, 0xBF800000BF800000;\n\t"
        "mov.b64 ra, {%2, %3};\n\t"
        "mov.b64 rb, {%4, %5};\n\t"
        "fma.rn.f32x2 rc, rb, rn, ra;\n\t"
        "mov.b64 {%0, %1}, rc;\n\t"
        "}"
        : "=f"(r.x), "=f"(r.y)
        : "f"(a.x), "f"(a.y), "f"(b.x), "f"(b.y));
    return r;
}

__device__ __forceinline__ float2 cmulf(float2 a, float2 b){
    return make_float2(fmaf(a.x, b.x, -a.y*b.y), fmaf(a.x, b.y, a.y*b.x));
}
// a * conj(b)
__device__ __forceinline__ float2 cmulf_cj(float2 a, float2 b){
    return make_float2(fmaf(a.x, b.x,  a.y*b.y), fmaf(a.y, b.x, -a.x*b.y));
}

// radix-8 DFT, natural order, unscaled; add/subs packed, cross terms scalar.
template<int SGN>
__device__ __forceinline__ void dft8(float2* v)
{
    const float C = 0.70710678118654752440f;
    const float S = (float)SGN;
    float2 u0 = f2add(v[0], v[4]), w0 = f2sub(v[0], v[4]);
    float2 u1 = f2add(v[1], v[5]), w1 = f2sub(v[1], v[5]);
    float2 u2 = f2add(v[2], v[6]), w2 = f2sub(v[2], v[6]);
    float2 u3 = f2add(v[3], v[7]), w3 = f2sub(v[3], v[7]);
    w1 = make_float2(C * (w1.x - S * w1.y),  C * (S * w1.x + w1.y));
    w3 = make_float2(-C * (w3.x + S * w3.y), C * (S * w3.x - w3.y));
    float2 p0 = f2add(u0, u2), q0 = f2sub(u0, u2);
    float2 p1 = f2add(u1, u3), t1 = f2sub(u1, u3);
    v[0] = f2add(p0, p1); v[4] = f2sub(p0, p1);
    v[2] = make_float2(q0.x - S * t1.y, q0.y + S * t1.x);
    v[6] = make_float2(q0.x + S * t1.y, q0.y - S * t1.x);
    float2 r0 = make_float2(w0.x - S * w2.y, w0.y + S * w2.x);
    float2 s0 = make_float2(w0.x + S * w2.y, w0.y - S * w2.x);
    float2 r1 = f2add(w1, w3), t2 = f2sub(w1, w3);
    v[1] = f2add(r0, r1); v[5] = f2sub(r0, r1);
    v[3] = make_float2(s0.x - S * t2.y, s0.y + S * t2.x);
    v[7] = make_float2(s0.x + S * t2.y, s0.y - S * t2.x);
}

// computed twiddles (stage0 only): powers via depth-3 tree
template<int SGN, int M>
__device__ __forceinline__ void twiddles(float2* v, int a)
{
    const float kAng = (float)SGN * 6.283185307179586f / (float)M;
    float sn, cs;
    __sincosf(kAng * (float)a, &sn, &cs);
    float2 w1 = make_float2(cs, sn);
    float2 w2 = cmulf(w1, w1);
    float2 w3 = cmulf(w2, w1);
    float2 w4 = cmulf(w2, w2);
    float2 w5 = cmulf(w3, w2);
    float2 w6 = cmulf(w3, w3);
    float2 w7 = cmulf(w4, w3);
    v[1] = cmulf(v[1], w1); v[2] = cmulf(v[2], w2);
    v[3] = cmulf(v[3], w3); v[4] = cmulf(v[4], w4);
    v[5] = cmulf(v[5], w5); v[6] = cmulf(v[6], w6);
    v[7] = cmulf(v[7], w7);
}

// table twiddle apply: tab[(j-1)*STRIDE + a] = exp(-2*pi*i * a*j / M).
// FWD: multiply; INV: multiply by conjugate.
template<bool FWD, int STRIDE>
__device__ __forceinline__ void twiddle_tab(float2* v, const float2* tab, int a)
{
    #pragma unroll
    for (int j = 1; j < 8; j++) {
        float2 w = tab[(j - 1) * STRIDE + a];
        v[j] = FWD ? cmulf(v[j], w) : cmulf_cj(v[j], w);
    }
}

// 8x8 transpose across 8 lanes (lane index a = t&7), 8 float2 regs.
__device__ __forceinline__ void transpose8(float2* v, int a)
{
    #pragma unroll
    for (int k = 1; k < 8; k <<= 1) {
        bool up = (a & k) != 0;
        #pragma unroll
        for (int j0 = 0; j0 < 8; j0++) {
            if ((j0 & k) == 0) {
                int j1 = j0 | k;
                float sx = up ? v[j0].x : v[j1].x;
                float sy = up ? v[j0].y : v[j1].y;
                sx = __shfl_xor_sync(0xffffffffu, sx, k);
                sy = __shfl_xor_sync(0xffffffffu, sy, k);
                if (up) { v[j0].x = sx; v[j0].y = sy; }
                else    { v[j1].x = sx; v[j1].y = sy; }
            }
        }
    }
}

// radix-8 pass at H=64 (M=512), twiddles from shared table
template<bool FWD>
__device__ __forceinline__ void stage64_tab(float2* s, const float2* tw64, int t)
{
    int base = (t >> 6) * 512 + (t & 63);
    int a    = t & 63;
    float2 v[8];
    #pragma unroll
    for (int i = 0; i < 8; i++)
        v[i] = s[SWZ(base + 64 * i)];
    if (FWD) { dft8<-1>(v); twiddle_tab<true, 64>(v, tw64, a); }
    else     { twiddle_tab<false, 64>(v, tw64, a); dft8<1>(v); }
    #pragma unroll
    for (int i = 0; i < 8; i++)
        s[SWZ(base + 64 * i)] = v[i];
}

// 64-thread named barrier: group = t>>6, ids 1..8
__device__ __forceinline__ void bar64(int t)
{
    asm volatile("bar.sync %0, 64;" :: "r"(1 + (t >> 6)) : "memory");
}

// ---------------- main kernel: 2 real channels per block ----------------
__global__ __launch_bounds__(TPB, 2)
void s4_fftconv_kernel(const float* __restrict__ x, float* __restrict__ y)
{
    __shared__ float2 s[LSEQ];
    __shared__ float2 tw64[7 * 64];   // exp(-2pi i a j/512), idx (j-1)*64+a
    __shared__ float2 tw8 [7 * 8];    // exp(-2pi i a j/64),  idx (j-1)*8+a
    const int t = threadIdx.x;
    const size_t base = (size_t)blockIdx.x * 2u * LSEQ;
    const float* x1 = x + base;
    const float* x2 = x + base + LSEQ;
    float* y1 = y + base;
    float* y2 = y + base + LSEQ;

    // ---- twiddle tables (covered by the first __syncthreads)
    if (t < 7 * 64) {
        int a = t & 63, j = (t >> 6) + 1;
        float sn, cs;
        __sincosf(-1.2271846303085130e-2f * (float)(a * j), &sn, &cs); // -2pi/512
        tw64[t] = make_float2(cs, sn);
        if (t < 7 * 8) {
            int a8 = t & 7, j8 = (t >> 3) + 1;
            __sincosf(-9.8174770424681038e-2f * (float)(a8 * j8), &sn, &cs); // -2pi/64
            tw8[t] = make_float2(cs, sn);
        }
    }

    float2 v[8];

    // ---- forward stage 0 (M=4096, H=512): global -> regs -> shared
    #pragma unroll
    for (int b = 0; b < 8; b++)
        v[b] = make_float2(x1[t + 512 * b], x2[t + 512 * b]);
    dft8<-1>(v);
    twiddles<-1, 4096>(v, t);
    #pragma unroll
    for (int j = 0; j < 8; j++)
        s[SWZ(t + 512 * j)] = v[j];
    __syncthreads();

    stage64_tab<true>(s, tw64, t);   // forward stage 1 (M=512, H=64)
    bar64(t);

    // ---- merged middle: fwd H=8 + transpose + fwd H=1 + Ksp + inv H=1 +
    //      transpose + inv H=8 — one smem round trip, all intra-warp
    {
        const int g = t >> 3;
        const int a = t & 7;
        const int mbase = 64 * g + a;
        #pragma unroll
        for (int i = 0; i < 8; i++)
            v[i] = s[SWZ(mbase + 8 * i)];
        float4 kk0, kk1, kk2, kk3;
        {
            const float4* K4 = reinterpret_cast<const float4*>(g_Ksp) + 4 * t;
            kk0 = __ldg(&K4[0]); kk1 = __ldg(&K4[1]);
            kk2 = __ldg(&K4[2]); kk3 = __ldg(&K4[3]);
        }
        dft8<-1>(v);
        twiddle_tab<true, 8>(v, tw8, a);
        transpose8(v, a);                 // v[d] = element 8t + d
        dft8<-1>(v);                      // fwd H=1 (no twiddle)
        v[0] = cmulf(v[0], make_float2(kk0.x, kk0.y));
        v[1] = cmulf(v[1], make_float2(kk0.z, kk0.w));
        v[2] = cmulf(v[2], make_float2(kk1.x, kk1.y));
        v[3] = cmulf(v[3], make_float2(kk1.z, kk1.w));
        v[4] = cmulf(v[4], make_float2(kk2.x, kk2.y));
        v[5] = cmulf(v[5], make_float2(kk2.z, kk2.w));
        v[6] = cmulf(v[6], make_float2(kk3.x, kk3.y));
        v[7] = cmulf(v[7], make_float2(kk3.z, kk3.w));
        dft8<1>(v);                       // inverse H=1
        transpose8(v, a);
        twiddle_tab<false, 8>(v, tw8, a);
        dft8<1>(v);                       // inverse H=8
        #pragma unroll
        for (int i = 0; i < 8; i++)
            s[SWZ(mbase + 8 * i)] = v[i];
    }
    bar64(t);

    stage64_tab<false>(s, tw64, t);  // inverse stage 1
    __syncthreads();

    // ---- inverse stage 0 (M=4096, H=512): shared -> regs -> global
    #pragma unroll
    for (int j = 0; j < 8; j++)
        v[j] = s[SWZ(t + 512 * j)];
    twiddles<1, 4096>(v, t);
    dft8<1>(v);
    #pragma unroll
    for (int b = 0; b < 8; b++) {
        y1[t + 512 * b] = v[b].x;
        y2[t + 512 * b] = v[b].y;
    }
}

extern "C" void kernel_launch(void* const* d_in, const int* in_sizes, int n_in,
                              void* d_out, int out_size)
{
    const float* x   = (const float*)d_in[0];
    const float* lre = (const float*)d_in[1];
    const float* lim = (const float*)d_in[2];
    const float* pre = (const float*)d_in[3];
    const float* pim = (const float*)d_in[4];
    const float* bre = (const float*)d_in[5];
    const float* bim = (const float*)d_in[6];
    const float* cre = (const float*)d_in[7];
    const float* cim = (const float*)d_in[8];
    float* y = (float*)d_out;

    compute_K_fused<<<(((LSEQ / 2 + 1) * 16) + 255) / 256, 256>>>(lre, lim, pre, pim, bre, bim, cre, cim);
    s4_fftconv_kernel<<<NPAIR, TPB>>>(x, y);
}

// round 11
// speedup vs baseline: 1.0300x; 1.0300x over previous
#include <cuda_runtime.h>
#include <math.h>

#define LSEQ   4096
#define NPAIR  2048      // 16*256/2
#define TPB    512

static __device__ float2 g_Ksp[LSEQ];

// base-8, 4-digit reversal
__device__ __forceinline__ int digitrev84(int i) {
    return ((i & 7) << 9) | (((i >> 3) & 7) << 6) |
           (((i >> 6) & 7) << 3) | ((i >> 9) & 7);
}

// ---------------- fused K + Ksp kernel (all fp32) ----------------
// 16 lanes per k: lanes 0-7 accumulate with +G (for k), lanes 8-15 with -G
// (for mirror L-k). Each lane handles 8 states. Uniform final algebra with
// T = +-t; halves combined via one xor-8 shuffle.
__global__ void compute_K_fused(const float* __restrict__ lre, const float* __restrict__ lim,
                                const float* __restrict__ pre, const float* __restrict__ pim,
                                const float* __restrict__ bre, const float* __restrict__ bim,
                                const float* __restrict__ cre, const float* __restrict__ cim)
{
    int gtid  = blockIdx.x * blockDim.x + threadIdx.x;
    int k     = gtid >> 4;          // 0..2048
    int sub   = gtid & 15;
    int lane8 = sub & 7;
    if (k > LSEQ / 2) return;

    const float t = tanf((float)k * 7.6699039394282221e-4f);  // pi/4096
    const float T = (sub & 8) ? -t : t;
    const float G = 2000.0f * T;

    float k00r=0,k00i=0,k01r=0,k01i=0,k10r=0,k10i=0,k11r=0,k11i=0;

    #pragma unroll
    for (int j = 0; j < 8; j++) {
        int n = lane8 * 8 + j;
        float lr = lre[n], li = lim[n];
        float pr = pre[n], pi_ = pim[n];
        float br = bre[n], bi = bim[n];
        float cr = cre[n], ci = cim[n];

        float nbr = fmaf(cr, br,  ci * bi),  nbi = fmaf(cr, bi, -ci * br);
        float npr = fmaf(cr, pr,  ci * pi_), npi = fmaf(cr, pi_, -ci * pr);
        float pbr = fmaf(pr, br,  pi_ * bi), pbi = fmaf(pr, bi, -pi_ * br);
        float pp  = fmaf(pr, pr,  pi_ * pi_);

        float ex = -lr, ey = G - li;
        float r  = 1.0f / fmaf(ex, ex, ey * ey);
        float dr = ex * r, di = -ey * r;
        k00r = fmaf(dr, nbr, fmaf(-di, nbi, k00r));
        k00i = fmaf(dr, nbi, fmaf( di, nbr, k00i));
        k01r = fmaf(dr, npr, fmaf(-di, npi, k01r));
        k01i = fmaf(dr, npi, fmaf( di, npr, k01i));
        k10r = fmaf(dr, pbr, fmaf(-di, pbi, k10r));
        k10i = fmaf(dr, pbi, fmaf( di, pbr, k10i));
        k11r = fmaf(dr, pp, k11r);
        k11i = fmaf(di, pp, k11i);
    }

    // reduce over the 8 lanes of this half (xor 1,2,4 stay within the half)
    #pragma unroll
    for (int m = 1; m < 8; m <<= 1) {
        k00r += __shfl_xor_sync(0xffffffffu, k00r, m);
        k00i += __shfl_xor_sync(0xffffffffu, k00i, m);
        k01r += __shfl_xor_sync(0xffffffffu, k01r, m);
        k01i += __shfl_xor_sync(0xffffffffu, k01i, m);
        k10r += __shfl_xor_sync(0xffffffffu, k10r, m);
        k10i += __shfl_xor_sync(0xffffffffu, k10i, m);
        k11r += __shfl_xor_sync(0xffffffffu, k11r, m);
        k11i += __shfl_xor_sync(0xffffffffu, k11i, m);
    }

    // lanes 0 and 8 compute their K in parallel
    float Kr = 0.0f, Ki = 0.0f;
    if (lane8 == 0) {
        float numr = k01r * k10r - k01i * k10i;
        float numi = k01r * k10i + k01i * k10r;
        float der  = 1.0f + k11r, dei = k11i;
        float dd   = 1.0f / fmaf(der, der, dei * dei);
        float ar = k00r - (numr * der + numi * dei) * dd;
        float ai = k00i - (numi * der - numr * dei) * dd;
        Kr = fmaf(-T, ai, ar);          // (1 + iT)*(ar + i ai)
        Ki = fmaf( T, ar, ai);
    }
    // swap halves: lane 0 receives lane 8's (mirror) K
    float Kmr = __shfl_xor_sync(0xffffffffu, Kr, 8);
    float Kmi = __shfl_xor_sync(0xffffffffu, Ki, 8);

    if (sub == 0) {
        const float sc = 0.5f / (float)LSEQ;
        float sr = (Kr + Kmr) * sc;
        float si = (Ki - Kmi) * sc;
        int mk = (LSEQ - k) & (LSEQ - 1);
        g_Ksp[digitrev84(k)]  = make_float2(sr,  si);
        g_Ksp[digitrev84(mk)] = make_float2(sr, -si);
    }
}

// ---------------- fp32 FFT machinery ----------------
// XOR swizzle: conflict-free for stride-512, stride-64 and stride-8 phases.
#define SWZ(i) ((i) ^ (((i) >> 3) & 0x38))

// Packed f32x2 complex add/sub (Blackwell FADD2/FFMA2).
__device__ __forceinline__ float2 f2add(float2 a, float2 b){
    float2 r;
    asm("{\n\t"
        ".reg .b64 ra, rb, rc;\n\t"
        "mov.b64 ra, {%2, %3};\n\t"
        "mov.b64 rb, {%4, %5};\n\t"
        "add.rn.f32x2 rc, ra, rb;\n\t"
        "mov.b64 {%0, %1}, rc;\n\t"
        "}"
        : "=f"(r.x), "=f"(r.y)
        : "f"(a.x), "f"(a.y), "f"(b.x), "f"(b.y));
    return r;
}
__device__ __forceinline__ float2 f2sub(float2 a, float2 b){
    float2 r;
    asm("{\n\t"
        ".reg .b64 ra, rb, rc, rn;\n\t"
        "mov.b64 rn, 0xBF800000BF800000;\n\t"
        "mov.b64 ra, {%2, %3};\n\t"
        "mov.b64 rb, {%4, %5};\n\t"
        "fma.rn.f32x2 rc, rb, rn, ra;\n\t"
        "mov.b64 {%0, %1}, rc;\n\t"
        "}"
        : "=f"(r.x), "=f"(r.y)
        : "f"(a.x), "f"(a.y), "f"(b.x), "f"(b.y));
    return r;
}

__device__ __forceinline__ float2 cmulf(float2 a, float2 b){
    return make_float2(fmaf(a.x, b.x, -a.y*b.y), fmaf(a.x, b.y, a.y*b.x));
}

// radix-8 DFT, natural order, unscaled; add/subs packed, cross terms scalar.
template<int SGN>
__device__ __forceinline__ void dft8(float2* v)
{
    const float C = 0.70710678118654752440f;
    const float S = (float)SGN;
    float2 u0 = f2add(v[0], v[4]), w0 = f2sub(v[0], v[4]);
    float2 u1 = f2add(v[1], v[5]), w1 = f2sub(v[1], v[5]);
    float2 u2 = f2add(v[2], v[6]), w2 = f2sub(v[2], v[6]);
    float2 u3 = f2add(v[3], v[7]), w3 = f2sub(v[3], v[7]);
    w1 = make_float2(C * (w1.x - S * w1.y),  C * (S * w1.x + w1.y));
    w3 = make_float2(-C * (w3.x + S * w3.y), C * (S * w3.x - w3.y));
    float2 p0 = f2add(u0, u2), q0 = f2sub(u0, u2);
    float2 p1 = f2add(u1, u3), t1 = f2sub(u1, u3);
    v[0] = f2add(p0, p1); v[4] = f2sub(p0, p1);
    v[2] = make_float2(q0.x - S * t1.y, q0.y + S * t1.x);
    v[6] = make_float2(q0.x + S * t1.y, q0.y - S * t1.x);
    float2 r0 = make_float2(w0.x - S * w2.y, w0.y + S * w2.x);
    float2 s0 = make_float2(w0.x + S * w2.y, w0.y - S * w2.x);
    float2 r1 = f2add(w1, w3), t2 = f2sub(w1, w3);
    v[1] = f2add(r0, r1); v[5] = f2sub(r0, r1);
    v[3] = make_float2(s0.x - S * t2.y, s0.y + S * t2.x);
    v[7] = make_float2(s0.x + S * t2.y, s0.y - S * t2.x);
}

// apply w_M^(SGN*a*j) to v[j], j=1..7 — powers via depth-3 tree
template<int SGN, int M>
__device__ __forceinline__ void twiddles(float2* v, int a)
{
    const float kAng = (float)SGN * 6.283185307179586f / (float)M;
    float sn, cs;
    __sincosf(kAng * (float)a, &sn, &cs);
    float2 w1 = make_float2(cs, sn);
    float2 w2 = cmulf(w1, w1);
    float2 w3 = cmulf(w2, w1);
    float2 w4 = cmulf(w2, w2);
    float2 w5 = cmulf(w3, w2);
    float2 w6 = cmulf(w3, w3);
    float2 w7 = cmulf(w4, w3);
    v[1] = cmulf(v[1], w1); v[2] = cmulf(v[2], w2);
    v[3] = cmulf(v[3], w3); v[4] = cmulf(v[4], w4);
    v[5] = cmulf(v[5], w5); v[6] = cmulf(v[6], w6);
    v[7] = cmulf(v[7], w7);
}

// 8x8 transpose across 8 lanes (lane index a = t&7), 8 float2 regs.
__device__ __forceinline__ void transpose8(float2* v, int a)
{
    #pragma unroll
    for (int k = 1; k < 8; k <<= 1) {
        bool up = (a & k) != 0;
        #pragma unroll
        for (int j0 = 0; j0 < 8; j0++) {
            if ((j0 & k) == 0) {
                int j1 = j0 | k;
                float sx = up ? v[j0].x : v[j1].x;
                float sy = up ? v[j0].y : v[j1].y;
                sx = __shfl_xor_sync(0xffffffffu, sx, k);
                sy = __shfl_xor_sync(0xffffffffu, sy, k);
                if (up) { v[j0].x = sx; v[j0].y = sy; }
                else    { v[j1].x = sx; v[j1].y = sy; }
            }
        }
    }
}

// one radix-8 pass in shared memory, stride H, sub-transform M=8H
template<int SGN, int H>
__device__ __forceinline__ void stage_sh(float2* s, int t)
{
    const int M = 8 * H;
    int base = (t / H) * M + (t % H);
    int a    = t % H;
    float2 v[8];
    #pragma unroll
    for (int i = 0; i < 8; i++)
        v[i] = s[SWZ(base + H * i)];
    if (SGN < 0) { dft8<SGN>(v); twiddles<SGN, M>(v, a); }
    else         { twiddles<SGN, M>(v, a); dft8<SGN>(v); }
    #pragma unroll
    for (int i = 0; i < 8; i++)
        s[SWZ(base + H * i)] = v[i];
}

// 64-thread named barrier: group = t>>6, ids 1..8
__device__ __forceinline__ void bar64(int t)
{
    asm volatile("bar.sync %0, 64;" :: "r"(1 + (t >> 6)) : "memory");
}

// ---------------- main kernel: 2 real channels per block ----------------
__global__ __launch_bounds__(TPB, 2)
void s4_fftconv_kernel(const float* __restrict__ x, float* __restrict__ y)
{
    __shared__ float2 s[LSEQ];
    const int t = threadIdx.x;
    const size_t base = (size_t)blockIdx.x * 2u * LSEQ;
    const float* x1 = x + base;
    const float* x2 = x + base + LSEQ;
    float* y1 = y + base;
    float* y2 = y + base + LSEQ;

    float2 v[8];

    // ---- forward stage 0 (M=4096, H=512): global -> regs -> shared
    #pragma unroll
    for (int b = 0; b < 8; b++)
        v[b] = make_float2(x1[t + 512 * b], x2[t + 512 * b]);
    dft8<-1>(v);
    twiddles<-1, 4096>(v, t);
    #pragma unroll
    for (int j = 0; j < 8; j++)
        s[SWZ(t + 512 * j)] = v[j];
    __syncthreads();

    stage_sh<-1, 64>(s, t);   // forward stage 1 (M=512, H=64)
    bar64(t);

    // ---- merged middle: fwd H=8 + transpose + fwd H=1 + Ksp + inv H=1 +
    //      transpose + inv H=8 — one smem round trip, all intra-warp
    {
        const int g = t >> 3;
        const int a = t & 7;
        const int mbase = 64 * g + a;
        #pragma unroll
        for (int i = 0; i < 8; i++)
            v[i] = s[SWZ(mbase + 8 * i)];
        float4 kk0, kk1, kk2, kk3;
        {
            const float4* K4 = reinterpret_cast<const float4*>(g_Ksp) + 4 * t;
            kk0 = __ldg(&K4[0]); kk1 = __ldg(&K4[1]);
            kk2 = __ldg(&K4[2]); kk3 = __ldg(&K4[3]);
        }
        dft8<-1>(v);
        twiddles<-1, 64>(v, a);
        transpose8(v, a);                 // v[d] = element 8t + d
        dft8<-1>(v);                      // fwd H=1 (no twiddle)
        v[0] = cmulf(v[0], make_float2(kk0.x, kk0.y));
        v[1] = cmulf(v[1], make_float2(kk0.z, kk0.w));
        v[2] = cmulf(v[2], make_float2(kk1.x, kk1.y));
        v[3] = cmulf(v[3], make_float2(kk1.z, kk1.w));
        v[4] = cmulf(v[4], make_float2(kk2.x, kk2.y));
        v[5] = cmulf(v[5], make_float2(kk2.z, kk2.w));
        v[6] = cmulf(v[6], make_float2(kk3.x, kk3.y));
        v[7] = cmulf(v[7], make_float2(kk3.z, kk3.w));
        dft8<1>(v);                       // inverse H=1
        transpose8(v, a);
        twiddles<1, 64>(v, a);
        dft8<1>(v);                       // inverse H=8
        #pragma unroll
        for (int i = 0; i < 8; i++)
            s[SWZ(mbase + 8 * i)] = v[i];
    }
    bar64(t);

    stage_sh<1, 64>(s, t);    // inverse stage 1
    __syncthreads();

    // ---- inverse stage 0 (M=4096, H=512): shared -> regs -> global
    #pragma unroll
    for (int j = 0; j < 8; j++)
        v[j] = s[SWZ(t + 512 * j)];
    twiddles<1, 4096>(v, t);
    dft8<1>(v);
    #pragma unroll
    for (int b = 0; b < 8; b++) {
        y1[t + 512 * b] = v[b].x;
        y2[t + 512 * b] = v[b].y;
    }
}

extern "C" void kernel_launch(void* const* d_in, const int* in_sizes, int n_in,
                              void* d_out, int out_size)
{
    const float* x   = (const float*)d_in[0];
    const float* lre = (const float*)d_in[1];
    const float* lim = (const float*)d_in[2];
    const float* pre = (const float*)d_in[3];
    const float* pim = (const float*)d_in[4];
    const float* bre = (const float*)d_in[5];
    const float* bim = (const float*)d_in[6];
    const float* cre = (const float*)d_in[7];
    const float* cim = (const float*)d_in[8];
    float* y = (float*)d_out;

    compute_K_fused<<<(((LSEQ / 2 + 1) * 16) + 255) / 256, 256>>>(lre, lim, pre, pim, bre, bim, cre, cim);
    s4_fftconv_kernel<<<NPAIR, TPB>>>(x, y);
}

// round 12
// speedup vs baseline: 1.0373x; 1.0071x over previous
#include <cuda_runtime.h>
#include <math.h>

#define LSEQ   4096
#define NPAIR  2048      // 16*256/2
#define TPB    512

static __device__ float2 g_Ksp[LSEQ];

// base-8, 4-digit reversal
__device__ __forceinline__ int digitrev84(int i) {
    return ((i & 7) << 9) | (((i >> 3) & 7) << 6) |
           (((i >> 6) & 7) << 3) | ((i >> 9) & 7);
}

// ---------------- fused K + Ksp kernel (all fp32) ----------------
// 16 lanes per k: lanes 0-7 accumulate with +G (for k), lanes 8-15 with -G
// (for mirror L-k). Each lane handles 8 states.
__global__ void compute_K_fused(const float* __restrict__ lre, const float* __restrict__ lim,
                                const float* __restrict__ pre, const float* __restrict__ pim,
                                const float* __restrict__ bre, const float* __restrict__ bim,
                                const float* __restrict__ cre, const float* __restrict__ cim)
{
    int gtid  = blockIdx.x * blockDim.x + threadIdx.x;
    int k     = gtid >> 4;          // 0..2048
    int sub   = gtid & 15;
    int lane8 = sub & 7;
    if (k > LSEQ / 2) return;

    const float t = tanf((float)k * 7.6699039394282221e-4f);  // pi/4096
    const float T = (sub & 8) ? -t : t;
    const float G = 2000.0f * T;

    float k00r=0,k00i=0,k01r=0,k01i=0,k10r=0,k10i=0,k11r=0,k11i=0;

    #pragma unroll
    for (int j = 0; j < 8; j++) {
        int n = lane8 * 8 + j;
        float lr = lre[n], li = lim[n];
        float pr = pre[n], pi_ = pim[n];
        float br = bre[n], bi = bim[n];
        float cr = cre[n], ci = cim[n];

        float nbr = fmaf(cr, br,  ci * bi),  nbi = fmaf(cr, bi, -ci * br);
        float npr = fmaf(cr, pr,  ci * pi_), npi = fmaf(cr, pi_, -ci * pr);
        float pbr = fmaf(pr, br,  pi_ * bi), pbi = fmaf(pr, bi, -pi_ * br);
        float pp  = fmaf(pr, pr,  pi_ * pi_);

        float ex = -lr, ey = G - li;
        float r  = 1.0f / fmaf(ex, ex, ey * ey);
        float dr = ex * r, di = -ey * r;
        k00r = fmaf(dr, nbr, fmaf(-di, nbi, k00r));
        k00i = fmaf(dr, nbi, fmaf( di, nbr, k00i));
        k01r = fmaf(dr, npr, fmaf(-di, npi, k01r));
        k01i = fmaf(dr, npi, fmaf( di, npr, k01i));
        k10r = fmaf(dr, pbr, fmaf(-di, pbi, k10r));
        k10i = fmaf(dr, pbi, fmaf( di, pbr, k10i));
        k11r = fmaf(dr, pp, k11r);
        k11i = fmaf(di, pp, k11i);
    }

    #pragma unroll
    for (int m = 1; m < 8; m <<= 1) {
        k00r += __shfl_xor_sync(0xffffffffu, k00r, m);
        k00i += __shfl_xor_sync(0xffffffffu, k00i, m);
        k01r += __shfl_xor_sync(0xffffffffu, k01r, m);
        k01i += __shfl_xor_sync(0xffffffffu, k01i, m);
        k10r += __shfl_xor_sync(0xffffffffu, k10r, m);
        k10i += __shfl_xor_sync(0xffffffffu, k10i, m);
        k11r += __shfl_xor_sync(0xffffffffu, k11r, m);
        k11i += __shfl_xor_sync(0xffffffffu, k11i, m);
    }

    float Kr = 0.0f, Ki = 0.0f;
    if (lane8 == 0) {
        float numr = k01r * k10r - k01i * k10i;
        float numi = k01r * k10i + k01i * k10r;
        float der  = 1.0f + k11r, dei = k11i;
        float dd   = 1.0f / fmaf(der, der, dei * dei);
        float ar = k00r - (numr * der + numi * dei) * dd;
        float ai = k00i - (numi * der - numr * dei) * dd;
        Kr = fmaf(-T, ai, ar);          // (1 + iT)*(ar + i ai)
        Ki = fmaf( T, ar, ai);
    }
    float Kmr = __shfl_xor_sync(0xffffffffu, Kr, 8);
    float Kmi = __shfl_xor_sync(0xffffffffu, Ki, 8);

    if (sub == 0) {
        const float sc = 0.5f / (float)LSEQ;
        float sr = (Kr + Kmr) * sc;
        float si = (Ki - Kmi) * sc;
        int mk = (LSEQ - k) & (LSEQ - 1);
        g_Ksp[digitrev84(k)]  = make_float2(sr,  si);
        g_Ksp[digitrev84(mk)] = make_float2(sr, -si);
    }
}

// ---------------- fp32 FFT machinery ----------------
// XOR swizzle: conflict-free for stride-512, stride-64 and stride-8 phases.
#define SWZ(i) ((i) ^ (((i) >> 3) & 0x38))

// Packed f32x2 complex add/sub (Blackwell FADD2/FFMA2).
__device__ __forceinline__ float2 f2add(float2 a, float2 b){
    float2 r;
    asm("{\n\t"
        ".reg .b64 ra, rb, rc;\n\t"
        "mov.b64 ra, {%2, %3};\n\t"
        "mov.b64 rb, {%4, %5};\n\t"
        "add.rn.f32x2 rc, ra, rb;\n\t"
        "mov.b64 {%0, %1}, rc;\n\t"
        "}"
        : "=f"(r.x), "=f"(r.y)
        : "f"(a.x), "f"(a.y), "f"(b.x), "f"(b.y));
    return r;
}
__device__ __forceinline__ float2 f2sub(float2 a, float2 b){
    float2 r;
    asm("{\n\t"
        ".reg .b64 ra, rb, rc, rn;\n\t"
        "mov.b64 rn, 0xBF800000BF800000;\n\t"
        "mov.b64 ra, {%2, %3};\n\t"
        "mov.b64 rb, {%4, %5};\n\t"
        "fma.rn.f32x2 rc, rb, rn, ra;\n\t"
        "mov.b64 {%0, %1}, rc;\n\t"
        "}"
        : "=f"(r.x), "=f"(r.y)
        : "f"(a.x), "f"(a.y), "f"(b.x), "f"(b.y));
    return r;
}

__device__ __forceinline__ float2 cmulf(float2 a, float2 b){
    return make_float2(fmaf(a.x, b.x, -a.y*b.y), fmaf(a.x, b.y, a.y*b.x));
}

// radix-8 DFT, natural order, unscaled; add/subs packed, cross terms scalar.
template<int SGN>
__device__ __forceinline__ void dft8(float2* v)
{
    const float C = 0.70710678118654752440f;
    const float S = (float)SGN;
    float2 u0 = f2add(v[0], v[4]), w0 = f2sub(v[0], v[4]);
    float2 u1 = f2add(v[1], v[5]), w1 = f2sub(v[1], v[5]);
    float2 u2 = f2add(v[2], v[6]), w2 = f2sub(v[2], v[6]);
    float2 u3 = f2add(v[3], v[7]), w3 = f2sub(v[3], v[7]);
    w1 = make_float2(C * (w1.x - S * w1.y),  C * (S * w1.x + w1.y));
    w3 = make_float2(-C * (w3.x + S * w3.y), C * (S * w3.x - w3.y));
    float2 p0 = f2add(u0, u2), q0 = f2sub(u0, u2);
    float2 p1 = f2add(u1, u3), t1 = f2sub(u1, u3);
    v[0] = f2add(p0, p1); v[4] = f2sub(p0, p1);
    v[2] = make_float2(q0.x - S * t1.y, q0.y + S * t1.x);
    v[6] = make_float2(q0.x + S * t1.y, q0.y - S * t1.x);
    float2 r0 = make_float2(w0.x - S * w2.y, w0.y + S * w2.x);
    float2 s0 = make_float2(w0.x + S * w2.y, w0.y - S * w2.x);
    float2 r1 = f2add(w1, w3), t2 = f2sub(w1, w3);
    v[1] = f2add(r0, r1); v[5] = f2sub(r0, r1);
    v[3] = make_float2(s0.x - S * t2.y, s0.y + S * t2.x);
    v[7] = make_float2(s0.x + S * t2.y, s0.y - S * t2.x);
}

// apply w_M^(SGN*a*j) to v[j], j=1..7 — powers via depth-3 tree
template<int SGN, int M>
__device__ __forceinline__ void twiddles(float2* v, int a)
{
    const float kAng = (float)SGN * 6.283185307179586f / (float)M;
    float sn, cs;
    __sincosf(kAng * (float)a, &sn, &cs);
    float2 w1 = make_float2(cs, sn);
    float2 w2 = cmulf(w1, w1);
    float2 w3 = cmulf(w2, w1);
    float2 w4 = cmulf(w2, w2);
    float2 w5 = cmulf(w3, w2);
    float2 w6 = cmulf(w3, w3);
    float2 w7 = cmulf(w4, w3);
    v[1] = cmulf(v[1], w1); v[2] = cmulf(v[2], w2);
    v[3] = cmulf(v[3], w3); v[4] = cmulf(v[4], w4);
    v[5] = cmulf(v[5], w5); v[6] = cmulf(v[6], w6);
    v[7] = cmulf(v[7], w7);
}

// 8x8 transpose across 8 lanes (lane index a = t&7), 8 float2 regs.
__device__ __forceinline__ void transpose8(float2* v, int a)
{
    #pragma unroll
    for (int k = 1; k < 8; k <<= 1) {
        bool up = (a & k) != 0;
        #pragma unroll
        for (int j0 = 0; j0 < 8; j0++) {
            if ((j0 & k) == 0) {
                int j1 = j0 | k;
                float sx = up ? v[j0].x : v[j1].x;
                float sy = up ? v[j0].y : v[j1].y;
                sx = __shfl_xor_sync(0xffffffffu, sx, k);
                sy = __shfl_xor_sync(0xffffffffu, sy, k);
                if (up) { v[j0].x = sx; v[j0].y = sy; }
                else    { v[j1].x = sx; v[j1].y = sy; }
            }
        }
    }
}

// one radix-8 pass in shared memory, stride H, sub-transform M=8H
template<int SGN, int H>
__device__ __forceinline__ void stage_sh(float2* s, int t)
{
    const int M = 8 * H;
    int base = (t / H) * M + (t % H);
    int a    = t % H;
    float2 v[8];
    #pragma unroll
    for (int i = 0; i < 8; i++)
        v[i] = s[SWZ(base + H * i)];
    if (SGN < 0) { dft8<SGN>(v); twiddles<SGN, M>(v, a); }
    else         { twiddles<SGN, M>(v, a); dft8<SGN>(v); }
    #pragma unroll
    for (int i = 0; i < 8; i++)
        s[SWZ(base + H * i)] = v[i];
}

// 64-thread named barrier: group = t>>6, ids 1..8
__device__ __forceinline__ void bar64(int t)
{
    asm volatile("bar.sync %0, 64;" :: "r"(1 + (t >> 6)) : "memory");
}

// ---------------- main kernel: 2 real channels per block ----------------
// Launched with PDL: everything before the Ksp loads overlaps compute_K.
__global__ __launch_bounds__(TPB, 2)
void s4_fftconv_kernel(const float* __restrict__ x, float* __restrict__ y)
{
    __shared__ float2 s[LSEQ];
    const int t = threadIdx.x;
    const size_t base = (size_t)blockIdx.x * 2u * LSEQ;
    const float* x1 = x + base;
    const float* x2 = x + base + LSEQ;
    float* y1 = y + base;
    float* y2 = y + base + LSEQ;

    float2 v[8];

    // ---- forward stage 0 (M=4096, H=512): global -> regs -> shared
    #pragma unroll
    for (int b = 0; b < 8; b++)
        v[b] = make_float2(x1[t + 512 * b], x2[t + 512 * b]);
    dft8<-1>(v);
    twiddles<-1, 4096>(v, t);
    #pragma unroll
    for (int j = 0; j < 8; j++)
        s[SWZ(t + 512 * j)] = v[j];
    __syncthreads();

    stage_sh<-1, 64>(s, t);   // forward stage 1 (M=512, H=64)
    bar64(t);

    // ---- merged middle: fwd H=8 + transpose + fwd H=1 + Ksp + inv H=1 +
    //      transpose + inv H=8 — one smem round trip, all intra-warp
    {
        const int g = t >> 3;
        const int a = t & 7;
        const int mbase = 64 * g + a;
        #pragma unroll
        for (int i = 0; i < 8; i++)
            v[i] = s[SWZ(mbase + 8 * i)];

        // wait for compute_K's grid (PDL); no-op when launched without PDL
        cudaGridDependencySynchronize();

        float4 kk0, kk1, kk2, kk3;
        {
            const float4* K4 = reinterpret_cast<const float4*>(g_Ksp) + 4 * t;
            kk0 = __ldg(&K4[0]); kk1 = __ldg(&K4[1]);
            kk2 = __ldg(&K4[2]); kk3 = __ldg(&K4[3]);
        }
        dft8<-1>(v);
        twiddles<-1, 64>(v, a);
        transpose8(v, a);                 // v[d] = element 8t + d
        dft8<-1>(v);                      // fwd H=1 (no twiddle)
        v[0] = cmulf(v[0], make_float2(kk0.x, kk0.y));
        v[1] = cmulf(v[1], make_float2(kk0.z, kk0.w));
        v[2] = cmulf(v[2], make_float2(kk1.x, kk1.y));
        v[3] = cmulf(v[3], make_float2(kk1.z, kk1.w));
        v[4] = cmulf(v[4], make_float2(kk2.x, kk2.y));
        v[5] = cmulf(v[5], make_float2(kk2.z, kk2.w));
        v[6] = cmulf(v[6], make_float2(kk3.x, kk3.y));
        v[7] = cmulf(v[7], make_float2(kk3.z, kk3.w));
        dft8<1>(v);                       // inverse H=1
        transpose8(v, a);
        twiddles<1, 64>(v, a);
        dft8<1>(v);                       // inverse H=8
        #pragma unroll
        for (int i = 0; i < 8; i++)
            s[SWZ(mbase + 8 * i)] = v[i];
    }
    bar64(t);

    stage_sh<1, 64>(s, t);    // inverse stage 1
    __syncthreads();

    // ---- inverse stage 0 (M=4096, H=512): shared -> regs -> global
    #pragma unroll
    for (int j = 0; j < 8; j++)
        v[j] = s[SWZ(t + 512 * j)];
    twiddles<1, 4096>(v, t);
    dft8<1>(v);
    #pragma unroll
    for (int b = 0; b < 8; b++) {
        y1[t + 512 * b] = v[b].x;
        y2[t + 512 * b] = v[b].y;
    }
}

extern "C" void kernel_launch(void* const* d_in, const int* in_sizes, int n_in,
                              void* d_out, int out_size)
{
    const float* x   = (const float*)d_in[0];
    const float* lre = (const float*)d_in[1];
    const float* lim = (const float*)d_in[2];
    const float* pre = (const float*)d_in[3];
    const float* pim = (const float*)d_in[4];
    const float* bre = (const float*)d_in[5];
    const float* bim = (const float*)d_in[6];
    const float* cre = (const float*)d_in[7];
    const float* cim = (const float*)d_in[8];
    float* y = (float*)d_out;

    compute_K_fused<<<(((LSEQ / 2 + 1) * 16) + 255) / 256, 256>>>(lre, lim, pre, pim, bre, bim, cre, cim);

    // fftconv with Programmatic Dependent Launch: overlaps its prologue
    // (x loads, stage0, stage64) with compute_K; gridsync before Ksp use.
    cudaLaunchConfig_t cfg = {};
    cfg.gridDim  = dim3(NPAIR, 1, 1);
    cfg.blockDim = dim3(TPB, 1, 1);
    cfg.dynamicSmemBytes = 0;
    cfg.stream = 0;   // legacy default stream (same as <<<>>> above)
    cudaLaunchAttribute attrs[1];
    attrs[0].id = cudaLaunchAttributeProgrammaticStreamSerialization;
    attrs[0].val.programmaticStreamSerializationAllowed = 1;
    cfg.attrs = attrs;
    cfg.numAttrs = 1;
    cudaError_t err = cudaLaunchKernelEx(&cfg, s4_fftconv_kernel, x, y);
    if (err != cudaSuccess) {
        // fallback: plain launch (PDL attr unsupported under this capture)
        s4_fftconv_kernel<<<NPAIR, TPB>>>(x, y);
    }
}